// round 1
// baseline (speedup 1.0000x reference)
#include <cuda_runtime.h>
#include <math.h>

#define SB   2048          // sequence length
#define NB   2             // batch
#define DD   1024          // model dim
#define HH   16            // heads
#define DH   64            // head dim
#define KSEL 16            // top-k tokens
#define MTOT (NB*SB)       // 4096 rows

// ---------------- scratch (static device globals; no allocation) ----------------
__device__ float g_q[MTOT*DD];
__device__ float g_k[MTOT*DD];
__device__ float g_v[MTOT*DD];
__device__ float g_att[MTOT*DD];
__device__ float g_hidden[MTOT*(DD/2)];
__device__ float g_imp[MTOT];
__device__ int   g_idx[NB*KSEL];
__device__ int   g_sel[MTOT];
__device__ float g_ksel[NB*KSEL*DD];
__device__ float g_vsel[NB*KSEL*DD];

// ---------------- fp32 SGEMM: C[M,N] = A[M,K] @ B[K,N] + bias, optional ReLU ----
// 128x128 block tile, BK=8, 256 threads, 8x8 per-thread micro-tile.
template<int RELU>
__global__ __launch_bounds__(256) void sgemm_bias(
    const float* __restrict__ A, const float* __restrict__ B,
    const float* __restrict__ bias, float* __restrict__ C,
    int M, int N, int K)
{
    __shared__ float As[8][132];   // padded to dodge bank conflicts on transposed store
    __shared__ float Bs[8][128];

    const int tid = threadIdx.x;
    const int ty  = tid >> 4;      // 0..15
    const int tx  = tid & 15;      // 0..15
    const int bm  = blockIdx.y * 128;
    const int bn  = blockIdx.x * 128;

    const int aRow = tid >> 1;           // 0..127
    const int aCol = (tid & 1) * 4;      // 0 or 4
    const int bRow = tid >> 5;           // 0..7
    const int bCol = (tid & 31) * 4;     // 0..124

    const float* Aptr = A + (size_t)(bm + aRow) * K + aCol;
    const float* Bptr = B + (size_t)bRow * N + bn + bCol;

    float acc[8][8];
    #pragma unroll
    for (int i = 0; i < 8; i++)
        #pragma unroll
        for (int j = 0; j < 8; j++) acc[i][j] = 0.f;

    for (int kt = 0; kt < K; kt += 8) {
        float4 a = *(const float4*)(Aptr + kt);
        As[aCol+0][aRow] = a.x;
        As[aCol+1][aRow] = a.y;
        As[aCol+2][aRow] = a.z;
        As[aCol+3][aRow] = a.w;
        float4 bv = *(const float4*)(Bptr + (size_t)kt * N);
        *(float4*)&Bs[bRow][bCol] = bv;
        __syncthreads();

        #pragma unroll
        for (int k = 0; k < 8; k++) {
            float rm[8], rn[8];
            *(float4*)&rm[0] = *(const float4*)&As[k][ty*8];
            *(float4*)&rm[4] = *(const float4*)&As[k][ty*8+4];
            *(float4*)&rn[0] = *(const float4*)&Bs[k][tx*8];
            *(float4*)&rn[4] = *(const float4*)&Bs[k][tx*8+4];
            #pragma unroll
            for (int i = 0; i < 8; i++)
                #pragma unroll
                for (int j = 0; j < 8; j++)
                    acc[i][j] = fmaf(rm[i], rn[j], acc[i][j]);
        }
        __syncthreads();
    }

    #pragma unroll
    for (int i = 0; i < 8; i++) {
        const int row = bm + ty*8 + i;
        #pragma unroll
        for (int j = 0; j < 8; j++) {
            const int col = bn + tx*8 + j;
            float v = acc[i][j] + bias[col];
            if (RELU) v = fmaxf(v, 0.f);
            C[(size_t)row * N + col] = v;
        }
    }
}

// ---------------- indexer layer 2: imp[r] = hidden[r,:] . Ws2  (sigmoid skipped:
// monotonic, top-k invariant). Warp per row. -----------------------------------
__global__ void indexer2_kernel(const float* __restrict__ hidden,
                                const float* __restrict__ Ws2)
{
    const int gw   = (blockIdx.x * blockDim.x + threadIdx.x) >> 5;
    const int lane = threadIdx.x & 31;
    if (gw >= MTOT) return;
    const float* hrow = hidden + (size_t)gw * (DD/2);
    float p = 0.f;
    #pragma unroll 4
    for (int c = lane; c < DD/2; c += 32) p = fmaf(hrow[c], Ws2[c], p);
    #pragma unroll
    for (int o = 16; o; o >>= 1) p += __shfl_xor_sync(0xffffffffu, p, o);
    if (lane == 0) g_imp[gw] = p;
}

// ---------------- top-K per batch (block per batch; iterative argmax) ----------
__global__ void topk_kernel()
{
    const int b   = blockIdx.x;
    const int tid = threadIdx.x;
    __shared__ float vals[SB];
    __shared__ float rv[256];
    __shared__ int   ri[256];

    for (int i = tid; i < SB; i += 256) {
        vals[i] = g_imp[b*SB + i];
        g_sel[b*SB + i] = 0;
    }
    __syncthreads();

    for (int t = 0; t < KSEL; t++) {
        float best = -INFINITY; int bi = SB;
        for (int i = tid; i < SB; i += 256) {
            float v = vals[i];
            if (v > best || (v == best && i < bi)) { best = v; bi = i; }
        }
        rv[tid] = best; ri[tid] = bi;
        __syncthreads();
        for (int s = 128; s > 0; s >>= 1) {
            if (tid < s) {
                if (rv[tid+s] > rv[tid] || (rv[tid+s] == rv[tid] && ri[tid+s] < ri[tid])) {
                    rv[tid] = rv[tid+s]; ri[tid] = ri[tid+s];
                }
            }
            __syncthreads();
        }
        if (tid == 0) {
            int w = ri[0];
            g_idx[b*KSEL + t] = w;
            g_sel[b*SB + w]   = 1;
            vals[w] = -INFINITY;
        }
        __syncthreads();
    }
}

// ---------------- gather selected K/V rows into compact [B, KSEL, D] -----------
__global__ void gather_kv_kernel()
{
    const int b = blockIdx.x >> 4;
    const int j = blockIdx.x & 15;
    const int src = g_idx[b*KSEL + j];
    const float4* kr = (const float4*)(g_k + (size_t)(b*SB + src) * DD);
    const float4* vr = (const float4*)(g_v + (size_t)(b*SB + src) * DD);
    float4* kd = (float4*)(g_ksel + (size_t)(b*KSEL + j) * DD);
    float4* vd = (float4*)(g_vsel + (size_t)(b*KSEL + j) * DD);
    kd[threadIdx.x] = kr[threadIdx.x];   // 256 threads * float4 = 1024 floats
    vd[threadIdx.x] = vr[threadIdx.x];
}

// ---------------- sparse attention: non-selected query rows --------------------
// For a non-selected query, only the KSEL selected keys survive the mask.
// One warp per (b, h, s); lane l owns dims {l, l+32}.
__global__ __launch_bounds__(256) void sparse_attn_kernel()
{
    const int lane = threadIdx.x & 31;
    const int gw   = (blockIdx.x * blockDim.x + threadIdx.x) >> 5;  // [0, NB*SB*HH)
    const int b = gw / (SB*HH);
    const int r = gw % (SB*HH);
    const int s = r / HH;
    const int h = r % HH;
    if (g_sel[b*SB + s]) return;   // selected rows handled by dense kernel (warp-uniform)

    const float* qrow = g_q + (size_t)(b*SB + s)*DD + h*DH;
    const float q0 = qrow[lane], q1 = qrow[lane + 32];

    float sc[KSEL];
    #pragma unroll
    for (int j = 0; j < KSEL; j++) {
        const float* kr = g_ksel + (size_t)(b*KSEL + j)*DD + h*DH;
        float p = q0*kr[lane] + q1*kr[lane + 32];
        #pragma unroll
        for (int o = 16; o; o >>= 1) p += __shfl_xor_sync(0xffffffffu, p, o);
        sc[j] = p * 0.125f;   // 1/sqrt(64)
    }
    float mx = -INFINITY;
    #pragma unroll
    for (int j = 0; j < KSEL; j++) mx = fmaxf(mx, sc[j]);
    float sum = 0.f;
    #pragma unroll
    for (int j = 0; j < KSEL; j++) { sc[j] = __expf(sc[j] - mx); sum += sc[j]; }
    const float inv = 1.f / sum;

    float o0 = 0.f, o1 = 0.f;
    #pragma unroll
    for (int j = 0; j < KSEL; j++) {
        const float* vr = g_vsel + (size_t)(b*KSEL + j)*DD + h*DH;
        o0 = fmaf(sc[j], vr[lane],      o0);
        o1 = fmaf(sc[j], vr[lane + 32], o1);
    }
    float* orow = g_att + (size_t)(b*SB + s)*DD + h*DH;
    orow[lane]      = o0 * inv;
    orow[lane + 32] = o1 * inv;
}

// ---------------- dense attention: the KSEL selected query rows ----------------
// Block per (b, h, selected-query). Full softmax over all SB keys.
__global__ __launch_bounds__(256) void dense_attn_kernel()
{
    const int bi = blockIdx.x;                 // [0, NB*HH*KSEL)
    const int b  = bi / (HH*KSEL);
    const int h  = (bi / KSEL) % HH;
    const int jq = bi % KSEL;
    const int s  = g_idx[b*KSEL + jq];

    __shared__ float qs[DH];
    __shared__ float sc[SB];        // 8 KB
    __shared__ float red[256];
    __shared__ float part[4][DH];

    const int tid  = threadIdx.x;
    const int lane = tid & 31;
    const int w    = tid >> 5;      // 8 warps

    if (tid < DH) qs[tid] = g_q[(size_t)(b*SB + s)*DD + h*DH + tid];
    __syncthreads();
    const float q0 = qs[lane], q1 = qs[lane + 32];

    // scores (warp per key, coalesced 2x128B per key)
    for (int j = w; j < SB; j += 8) {
        const float* kr = g_k + (size_t)(b*SB + j)*DD + h*DH;
        float p = q0*kr[lane] + q1*kr[lane + 32];
        #pragma unroll
        for (int o = 16; o; o >>= 1) p += __shfl_xor_sync(0xffffffffu, p, o);
        if (lane == 0) sc[j] = p * 0.125f;
    }
    __syncthreads();

    // max
    float mx = -INFINITY;
    for (int j = tid; j < SB; j += 256) mx = fmaxf(mx, sc[j]);
    red[tid] = mx; __syncthreads();
    for (int st = 128; st; st >>= 1) {
        if (tid < st) red[tid] = fmaxf(red[tid], red[tid + st]);
        __syncthreads();
    }
    mx = red[0];
    __syncthreads();

    // exp + sum
    float lsum = 0.f;
    for (int j = tid; j < SB; j += 256) {
        float e = __expf(sc[j] - mx);
        sc[j] = e;
        lsum += e;
    }
    red[tid] = lsum; __syncthreads();
    for (int st = 128; st; st >>= 1) {
        if (tid < st) red[tid] += red[tid + st];
        __syncthreads();
    }
    const float inv = 1.f / red[0];

    // out[d] = sum_j sc[j] * v[j][d]; thread = (chunk c, dim d), coalesced over d
    const int d = tid & 63;
    const int c = tid >> 6;         // 0..3
    float acc = 0.f;
    const int j0 = c * (SB/4), j1 = j0 + (SB/4);
    for (int j = j0; j < j1; j++)
        acc = fmaf(sc[j], g_v[(size_t)(b*SB + j)*DD + h*DH + d], acc);
    part[c][d] = acc;
    __syncthreads();
    if (tid < DH) {
        float r = (part[0][tid] + part[1][tid] + part[2][tid] + part[3][tid]) * inv;
        g_att[(size_t)(b*SB + s)*DD + h*DH + tid] = r;
    }
}

// ---------------- launch -------------------------------------------------------
extern "C" void kernel_launch(void* const* d_in, const int* in_sizes, int n_in,
                              void* d_out, int out_size)
{
    const float* x   = (const float*)d_in[0];
    const float* Wq  = (const float*)d_in[1];
    const float* bq  = (const float*)d_in[2];
    const float* Wk  = (const float*)d_in[3];
    const float* bk  = (const float*)d_in[4];
    const float* Wv  = (const float*)d_in[5];
    const float* bv  = (const float*)d_in[6];
    const float* Wo  = (const float*)d_in[7];
    const float* bo  = (const float*)d_in[8];
    const float* Ws1 = (const float*)d_in[9];
    const float* bs1 = (const float*)d_in[10];
    const float* Ws2 = (const float*)d_in[11];
    float* out = (float*)d_out;

    float *q, *k, *v, *att, *hidden;
    cudaGetSymbolAddress((void**)&q,      g_q);
    cudaGetSymbolAddress((void**)&k,      g_k);
    cudaGetSymbolAddress((void**)&v,      g_v);
    cudaGetSymbolAddress((void**)&att,    g_att);
    cudaGetSymbolAddress((void**)&hidden, g_hidden);

    dim3 t256(256);
    dim3 gFull(DD/128, MTOT/128);    // 8 x 32
    dim3 gHalf((DD/2)/128, MTOT/128);// 4 x 32

    // QKV + indexer layer 1 (independent GEMMs)
    sgemm_bias<0><<<gFull, t256>>>(x, Wq, bq, q, MTOT, DD, DD);
    sgemm_bias<0><<<gFull, t256>>>(x, Wk, bk, k, MTOT, DD, DD);
    sgemm_bias<0><<<gFull, t256>>>(x, Wv, bv, v, MTOT, DD, DD);
    sgemm_bias<1><<<gHalf, t256>>>(x, Ws1, bs1, hidden, MTOT, DD/2, DD);

    // indexer layer 2 -> importance logits (sigmoid skipped; monotonic)
    indexer2_kernel<<<(MTOT*32 + 255)/256, t256>>>(hidden, Ws2);

    // top-k + gather
    topk_kernel<<<NB, t256>>>();
    gather_kv_kernel<<<NB*KSEL, t256>>>();

    // attention (sparse rows + dense selected rows cover all rows exactly once)
    sparse_attn_kernel<<<(NB*SB*HH)/8, t256>>>();
    dense_attn_kernel<<<NB*HH*KSEL, t256>>>();

    // output projection -> d_out
    sgemm_bias<0><<<gFull, t256>>>(att, Wo, bo, out, MTOT, DD, DD);
}

// round 3
// speedup vs baseline: 1.0746x; 1.0746x over previous
#include <cuda_runtime.h>
#include <math.h>
#include <stdint.h>

#define SB   2048          // sequence length
#define NB   2             // batch
#define DD   1024          // model dim
#define HH   16            // heads
#define DH   64            // head dim
#define KSEL 16            // top-k tokens
#define MTOT (NB*SB)       // 4096 rows

// ---------------- scratch (static device globals; no allocation) ----------------
__device__ float g_q[MTOT*DD];
__device__ float g_k[MTOT*DD];
__device__ float g_v[MTOT*DD];
__device__ float g_att[MTOT*DD];
__device__ float g_hidden[MTOT*(DD/2)];
__device__ float g_imp[MTOT];
__device__ int   g_idx[NB*KSEL];
__device__ int   g_sel[MTOT];
__device__ float g_ksel[NB*KSEL*DD];
__device__ float g_vsel[NB*KSEL*DD];

// ---------------- tf32 helpers -------------------------------------------------
__device__ __forceinline__ uint32_t f2tf32(float x) {
    uint32_t r;
    asm("cvt.rna.tf32.f32 %0, %1;" : "=r"(r) : "f"(x));
    return r;
}

__device__ __forceinline__ void mma_tf32(float* d, const uint32_t* a, const uint32_t* b) {
    asm volatile(
        "mma.sync.aligned.m16n8k8.row.col.f32.tf32.tf32.f32 "
        "{%0,%1,%2,%3}, {%4,%5,%6,%7}, {%8,%9}, {%0,%1,%2,%3};"
        : "+f"(d[0]), "+f"(d[1]), "+f"(d[2]), "+f"(d[3])
        : "r"(a[0]), "r"(a[1]), "r"(a[2]), "r"(a[3]), "r"(b[0]), "r"(b[1]));
}

// ---------------- 3xTF32 tensor-core GEMM: C = A[M,K] @ B[K,N] + bias ----------
// Split each operand into tf32 hi + lo; C = hi*hi + hi*lo + lo*hi (~fp32 accuracy).
// 128x128 block tile, BK=16, 256 threads, warp tile 64x32 (4x4 m16n8k8 tiles).
// Register-staged software pipeline: next k-tile gmem loads overlap current MMAs.
#define BM 128
#define BN 128
#define BKT 16

template<int RELU>
__global__ __launch_bounds__(256, 2) void gemm_tf32x3(
    const float* __restrict__ A, const float* __restrict__ B,
    const float* __restrict__ bias, float* __restrict__ C,
    int M, int N, int K)
{
    __shared__ float Ah[BM][BKT + 4];   // pad 4: conflict-free fragment loads
    __shared__ float Al[BM][BKT + 4];
    __shared__ float Bh[BKT][BN + 8];   // pad 8: conflict-free fragment loads
    __shared__ float Bl[BKT][BN + 8];

    const int tid  = threadIdx.x;
    const int warp = tid >> 5;
    const int lane = tid & 31;
    const int wm   = warp >> 2;         // 0..1
    const int wn   = warp & 3;          // 0..3
    const int mW   = wm * 64;
    const int nW   = wn * 32;
    const int g    = lane >> 2;         // 0..7
    const int t    = lane & 3;          // 0..3

    const int bm = blockIdx.y * BM;
    const int bn = blockIdx.x * BN;

    // gmem staging indices
    const int arow = tid >> 1;          // 0..127
    const int ac4  = tid & 1;           // float4 slot (+2 per i)
    const int brow = tid >> 4;          // 0..15
    const int bc4  = tid & 15;          // float4 slot (+16 per i)

    const float* Abase = A + (size_t)(bm + arow) * K;
    const float* Bbase = B + (size_t)brow * N + bn;

    float acc[4][4][4];
    #pragma unroll
    for (int mt = 0; mt < 4; mt++)
        #pragma unroll
        for (int nt = 0; nt < 4; nt++)
            #pragma unroll
            for (int r = 0; r < 4; r++) acc[mt][nt][r] = 0.f;

    // preload k-tile 0 into registers
    float4 pa[2], pb[2];
    #pragma unroll
    for (int i = 0; i < 2; i++) {
        pa[i] = *(const float4*)(Abase + (ac4 + 2 * i) * 4);
        pb[i] = *(const float4*)(Bbase + (bc4 + 16 * i) * 4);
    }

    for (int kt = 0; kt < K; kt += BKT) {
        // convert + store staged registers into smem (hi/lo split)
        #pragma unroll
        for (int i = 0; i < 2; i++) {
            const int c = (ac4 + 2 * i) * 4;
            float f[4] = {pa[i].x, pa[i].y, pa[i].z, pa[i].w};
            #pragma unroll
            for (int j = 0; j < 4; j++) {
                uint32_t hb = f2tf32(f[j]);
                float hf = __uint_as_float(hb);
                uint32_t lb = f2tf32(f[j] - hf);
                Ah[arow][c + j] = hf;
                Al[arow][c + j] = __uint_as_float(lb);
            }
        }
        #pragma unroll
        for (int i = 0; i < 2; i++) {
            const int c = (bc4 + 16 * i) * 4;
            float f[4] = {pb[i].x, pb[i].y, pb[i].z, pb[i].w};
            #pragma unroll
            for (int j = 0; j < 4; j++) {
                uint32_t hb = f2tf32(f[j]);
                float hf = __uint_as_float(hb);
                uint32_t lb = f2tf32(f[j] - hf);
                Bh[brow][c + j] = hf;
                Bl[brow][c + j] = __uint_as_float(lb);
            }
        }
        __syncthreads();

        // prefetch next k-tile (latency hidden behind the MMA loop below)
        if (kt + BKT < K) {
            const int kn = kt + BKT;
            #pragma unroll
            for (int i = 0; i < 2; i++) {
                pa[i] = *(const float4*)(Abase + kn + (ac4 + 2 * i) * 4);
                pb[i] = *(const float4*)(Bbase + (size_t)kn * N + (bc4 + 16 * i) * 4);
            }
        }

        #pragma unroll
        for (int ks = 0; ks < 2; ks++) {
            const int k0 = ks * 8;
            uint32_t aH[4][4], aL[4][4];
            #pragma unroll
            for (int mt = 0; mt < 4; mt++) {
                const int r0 = mW + mt * 16 + g;
                aH[mt][0] = __float_as_uint(Ah[r0    ][k0 + t    ]);
                aH[mt][1] = __float_as_uint(Ah[r0 + 8][k0 + t    ]);
                aH[mt][2] = __float_as_uint(Ah[r0    ][k0 + t + 4]);
                aH[mt][3] = __float_as_uint(Ah[r0 + 8][k0 + t + 4]);
                aL[mt][0] = __float_as_uint(Al[r0    ][k0 + t    ]);
                aL[mt][1] = __float_as_uint(Al[r0 + 8][k0 + t    ]);
                aL[mt][2] = __float_as_uint(Al[r0    ][k0 + t + 4]);
                aL[mt][3] = __float_as_uint(Al[r0 + 8][k0 + t + 4]);
            }
            #pragma unroll
            for (int nt = 0; nt < 4; nt++) {
                const int c0 = nW + nt * 8 + g;
                uint32_t bH[2], bL[2];
                bH[0] = __float_as_uint(Bh[k0 + t    ][c0]);
                bH[1] = __float_as_uint(Bh[k0 + t + 4][c0]);
                bL[0] = __float_as_uint(Bl[k0 + t    ][c0]);
                bL[1] = __float_as_uint(Bl[k0 + t + 4][c0]);
                #pragma unroll
                for (int mt = 0; mt < 4; mt++) {
                    mma_tf32(acc[mt][nt], aH[mt], bH);
                    mma_tf32(acc[mt][nt], aH[mt], bL);
                    mma_tf32(acc[mt][nt], aL[mt], bH);
                }
            }
        }
        __syncthreads();
    }

    // epilogue: bias (+ optional ReLU), float2 stores
    #pragma unroll
    for (int mt = 0; mt < 4; mt++) {
        const int r0 = bm + mW + mt * 16 + g;
        #pragma unroll
        for (int nt = 0; nt < 4; nt++) {
            const int c0 = bn + nW + nt * 8 + 2 * t;
            const float b0 = bias[c0], b1 = bias[c0 + 1];
            float v0 = acc[mt][nt][0] + b0;
            float v1 = acc[mt][nt][1] + b1;
            float v2 = acc[mt][nt][2] + b0;
            float v3 = acc[mt][nt][3] + b1;
            if (RELU) {
                v0 = fmaxf(v0, 0.f); v1 = fmaxf(v1, 0.f);
                v2 = fmaxf(v2, 0.f); v3 = fmaxf(v3, 0.f);
            }
            *(float2*)(C + (size_t)r0 * N + c0)       = make_float2(v0, v1);
            *(float2*)(C + (size_t)(r0 + 8) * N + c0) = make_float2(v2, v3);
        }
    }
}

// ---------------- indexer layer 2: imp[r] = hidden[r,:] . Ws2 ------------------
__global__ void indexer2_kernel(const float* __restrict__ hidden,
                                const float* __restrict__ Ws2)
{
    const int gw   = (blockIdx.x * blockDim.x + threadIdx.x) >> 5;
    const int lane = threadIdx.x & 31;
    if (gw >= MTOT) return;
    const float* hrow = hidden + (size_t)gw * (DD/2);
    float p = 0.f;
    #pragma unroll 4
    for (int c = lane; c < DD/2; c += 32) p = fmaf(hrow[c], Ws2[c], p);
    #pragma unroll
    for (int o = 16; o; o >>= 1) p += __shfl_xor_sync(0xffffffffu, p, o);
    if (lane == 0) g_imp[gw] = p;
}

// ---------------- top-K per batch (block per batch; iterative argmax) ----------
__global__ void topk_kernel()
{
    const int b   = blockIdx.x;
    const int tid = threadIdx.x;
    __shared__ float vals[SB];
    __shared__ float rv[256];
    __shared__ int   ri[256];

    for (int i = tid; i < SB; i += 256) {
        vals[i] = g_imp[b*SB + i];
        g_sel[b*SB + i] = 0;
    }
    __syncthreads();

    for (int tsel = 0; tsel < KSEL; tsel++) {
        float best = -INFINITY; int bi = SB;
        for (int i = tid; i < SB; i += 256) {
            float v = vals[i];
            if (v > best || (v == best && i < bi)) { best = v; bi = i; }
        }
        rv[tid] = best; ri[tid] = bi;
        __syncthreads();
        for (int s = 128; s > 0; s >>= 1) {
            if (tid < s) {
                if (rv[tid+s] > rv[tid] || (rv[tid+s] == rv[tid] && ri[tid+s] < ri[tid])) {
                    rv[tid] = rv[tid+s]; ri[tid] = ri[tid+s];
                }
            }
            __syncthreads();
        }
        if (tid == 0) {
            int w = ri[0];
            g_idx[b*KSEL + tsel] = w;
            g_sel[b*SB + w]      = 1;
            vals[w] = -INFINITY;
        }
        __syncthreads();
    }
}

// ---------------- gather selected K/V rows into compact [B, KSEL, D] -----------
__global__ void gather_kv_kernel()
{
    const int b = blockIdx.x >> 4;
    const int j = blockIdx.x & 15;
    const int src = g_idx[b*KSEL + j];
    const float4* kr = (const float4*)(g_k + (size_t)(b*SB + src) * DD);
    const float4* vr = (const float4*)(g_v + (size_t)(b*SB + src) * DD);
    float4* kd = (float4*)(g_ksel + (size_t)(b*KSEL + j) * DD);
    float4* vd = (float4*)(g_vsel + (size_t)(b*KSEL + j) * DD);
    kd[threadIdx.x] = kr[threadIdx.x];
    vd[threadIdx.x] = vr[threadIdx.x];
}

// ---------------- sparse attention: non-selected query rows --------------------
__global__ __launch_bounds__(256) void sparse_attn_kernel()
{
    const int lane = threadIdx.x & 31;
    const int gw   = (blockIdx.x * blockDim.x + threadIdx.x) >> 5;
    const int b = gw / (SB*HH);
    const int r = gw % (SB*HH);
    const int s = r / HH;
    const int h = r % HH;
    if (g_sel[b*SB + s]) return;   // warp-uniform

    const float* qrow = g_q + (size_t)(b*SB + s)*DD + h*DH;
    const float q0 = qrow[lane], q1 = qrow[lane + 32];

    float sc[KSEL];
    #pragma unroll
    for (int j = 0; j < KSEL; j++) {
        const float* kr = g_ksel + (size_t)(b*KSEL + j)*DD + h*DH;
        float p = q0*kr[lane] + q1*kr[lane + 32];
        #pragma unroll
        for (int o = 16; o; o >>= 1) p += __shfl_xor_sync(0xffffffffu, p, o);
        sc[j] = p * 0.125f;
    }
    float mx = -INFINITY;
    #pragma unroll
    for (int j = 0; j < KSEL; j++) mx = fmaxf(mx, sc[j]);
    float sum = 0.f;
    #pragma unroll
    for (int j = 0; j < KSEL; j++) { sc[j] = __expf(sc[j] - mx); sum += sc[j]; }
    const float inv = 1.f / sum;

    float o0 = 0.f, o1 = 0.f;
    #pragma unroll
    for (int j = 0; j < KSEL; j++) {
        const float* vr = g_vsel + (size_t)(b*KSEL + j)*DD + h*DH;
        o0 = fmaf(sc[j], vr[lane],      o0);
        o1 = fmaf(sc[j], vr[lane + 32], o1);
    }
    float* orow = g_att + (size_t)(b*SB + s)*DD + h*DH;
    orow[lane]      = o0 * inv;
    orow[lane + 32] = o1 * inv;
}

// ---------------- dense attention: the KSEL selected query rows ----------------
__global__ __launch_bounds__(256) void dense_attn_kernel()
{
    const int bi = blockIdx.x;
    const int b  = bi / (HH*KSEL);
    const int h  = (bi / KSEL) % HH;
    const int jq = bi % KSEL;
    const int s  = g_idx[b*KSEL + jq];

    __shared__ float qs[DH];
    __shared__ float sc[SB];
    __shared__ float red[256];
    __shared__ float part[4][DH];

    const int tid  = threadIdx.x;
    const int lane = tid & 31;
    const int w    = tid >> 5;

    if (tid < DH) qs[tid] = g_q[(size_t)(b*SB + s)*DD + h*DH + tid];
    __syncthreads();
    const float q0 = qs[lane], q1 = qs[lane + 32];

    for (int j = w; j < SB; j += 8) {
        const float* kr = g_k + (size_t)(b*SB + j)*DD + h*DH;
        float p = q0*kr[lane] + q1*kr[lane + 32];
        #pragma unroll
        for (int o = 16; o; o >>= 1) p += __shfl_xor_sync(0xffffffffu, p, o);
        if (lane == 0) sc[j] = p * 0.125f;
    }
    __syncthreads();

    float mx = -INFINITY;
    for (int j = tid; j < SB; j += 256) mx = fmaxf(mx, sc[j]);
    red[tid] = mx; __syncthreads();
    for (int st = 128; st; st >>= 1) {
        if (tid < st) red[tid] = fmaxf(red[tid], red[tid + st]);
        __syncthreads();
    }
    mx = red[0];
    __syncthreads();

    float lsum = 0.f;
    for (int j = tid; j < SB; j += 256) {
        float e = __expf(sc[j] - mx);
        sc[j] = e;
        lsum += e;
    }
    red[tid] = lsum; __syncthreads();
    for (int st = 128; st; st >>= 1) {
        if (tid < st) red[tid] += red[tid + st];
        __syncthreads();
    }
    const float inv = 1.f / red[0];

    const int d = tid & 63;
    const int c = tid >> 6;
    float acc = 0.f;
    const int j0 = c * (SB/4), j1 = j0 + (SB/4);
    for (int j = j0; j < j1; j++)
        acc = fmaf(sc[j], g_v[(size_t)(b*SB + j)*DD + h*DH + d], acc);
    part[c][d] = acc;
    __syncthreads();
    if (tid < DH) {
        float r = (part[0][tid] + part[1][tid] + part[2][tid] + part[3][tid]) * inv;
        g_att[(size_t)(b*SB + s)*DD + h*DH + tid] = r;
    }
}

// ---------------- launch -------------------------------------------------------
extern "C" void kernel_launch(void* const* d_in, const int* in_sizes, int n_in,
                              void* d_out, int out_size)
{
    const float* x   = (const float*)d_in[0];
    const float* Wq  = (const float*)d_in[1];
    const float* bq  = (const float*)d_in[2];
    const float* Wk  = (const float*)d_in[3];
    const float* bk  = (const float*)d_in[4];
    const float* Wv  = (const float*)d_in[5];
    const float* bv  = (const float*)d_in[6];
    const float* Wo  = (const float*)d_in[7];
    const float* bo  = (const float*)d_in[8];
    const float* Ws1 = (const float*)d_in[9];
    const float* bs1 = (const float*)d_in[10];
    const float* Ws2 = (const float*)d_in[11];
    float* out = (float*)d_out;

    float *q, *k, *v, *att, *hidden;
    cudaGetSymbolAddress((void**)&q,      g_q);
    cudaGetSymbolAddress((void**)&k,      g_k);
    cudaGetSymbolAddress((void**)&v,      g_v);
    cudaGetSymbolAddress((void**)&att,    g_att);
    cudaGetSymbolAddress((void**)&hidden, g_hidden);

    dim3 t256(256);
    dim3 gFull(DD/BN, MTOT/BM);        // 8 x 32
    dim3 gHalf((DD/2)/BN, MTOT/BM);    // 4 x 32

    // QKV + indexer layer 1 (tensor-core 3xTF32)
    gemm_tf32x3<0><<<gFull, t256>>>(x, Wq, bq, q, MTOT, DD, DD);
    gemm_tf32x3<0><<<gFull, t256>>>(x, Wk, bk, k, MTOT, DD, DD);
    gemm_tf32x3<0><<<gFull, t256>>>(x, Wv, bv, v, MTOT, DD, DD);
    gemm_tf32x3<1><<<gHalf, t256>>>(x, Ws1, bs1, hidden, MTOT, DD/2, DD);

    // indexer layer 2 -> importance logits (sigmoid skipped; monotonic)
    indexer2_kernel<<<(MTOT*32 + 255)/256, t256>>>(hidden, Ws2);

    // top-k + gather
    topk_kernel<<<NB, t256>>>();
    gather_kv_kernel<<<NB*KSEL, t256>>>();

    // attention (sparse rows + dense selected rows cover all rows exactly once)
    sparse_attn_kernel<<<(NB*SB*HH)/8, t256>>>();
    dense_attn_kernel<<<NB*HH*KSEL, t256>>>();

    // output projection -> d_out (tensor-core 3xTF32)
    gemm_tf32x3<0><<<gFull, t256>>>(att, Wo, bo, out, MTOT, DD, DD);
}

// round 4
// speedup vs baseline: 2.4118x; 2.2443x over previous
#include <cuda_runtime.h>
#include <cuda_bf16.h>
#include <math.h>
#include <stdint.h>

#define SB   2048          // sequence length
#define NB   2             // batch
#define DD   1024          // model dim
#define HH   16            // heads
#define DH   64            // head dim
#define KSEL 16            // top-k tokens
#define MTOT (NB*SB)       // 4096 rows

// ---------------- scratch (static device globals; no allocation) ----------------
__device__ float g_q[MTOT*DD];
__device__ float g_k[MTOT*DD];
__device__ float g_v[MTOT*DD];
__device__ float g_att[MTOT*DD];
__device__ float g_hidden[MTOT*(DD/2)];
__device__ float g_imp[MTOT];
__device__ int   g_idx[NB*KSEL];
__device__ int   g_sel[MTOT];
__device__ float g_ksel[NB*KSEL*DD];
__device__ float g_vsel[NB*KSEL*DD];

// bf16 hi/lo split arrays
__device__ unsigned short g_xh[MTOT*DD],  g_xl[MTOT*DD];
__device__ unsigned short g_wqh[DD*DD],   g_wql[DD*DD];
__device__ unsigned short g_wkh[DD*DD],   g_wkl[DD*DD];
__device__ unsigned short g_wvh[DD*DD],   g_wvl[DD*DD];
__device__ unsigned short g_ws1h[DD*DD/2], g_ws1l[DD*DD/2];
__device__ unsigned short g_woh[DD*DD],   g_wol[DD*DD];
__device__ unsigned short g_ath[MTOT*DD], g_atl[MTOT*DD];

// ---------------- asm helpers --------------------------------------------------
#define CPA16(dst, src) \
    asm volatile("cp.async.cg.shared.global [%0], [%1], 16;" :: "r"(dst), "l"(src))

#define LDSM4(r, addr) \
    asm volatile("ldmatrix.sync.aligned.m8n8.x4.shared.b16 {%0,%1,%2,%3}, [%4];" \
        : "=r"((r)[0]), "=r"((r)[1]), "=r"((r)[2]), "=r"((r)[3]) : "r"(addr))

#define LDSM4T(r, addr) \
    asm volatile("ldmatrix.sync.aligned.m8n8.x4.trans.shared.b16 {%0,%1,%2,%3}, [%4];" \
        : "=r"((r)[0]), "=r"((r)[1]), "=r"((r)[2]), "=r"((r)[3]) : "r"(addr))

#define MMA_BF16(d, a, b) \
    asm volatile("mma.sync.aligned.m16n8k16.row.col.f32.bf16.bf16.f32 " \
        "{%0,%1,%2,%3}, {%4,%5,%6,%7}, {%8,%9}, {%0,%1,%2,%3};" \
        : "+f"((d)[0]), "+f"((d)[1]), "+f"((d)[2]), "+f"((d)[3]) \
        : "r"((a)[0]), "r"((a)[1]), "r"((a)[2]), "r"((a)[3]), "r"((b)[0]), "r"((b)[1]))

// ---------------- fp32 -> bf16 hi/lo converters --------------------------------
__device__ __forceinline__ void conv_seg(const float* __restrict__ in,
                                         unsigned short* __restrict__ h,
                                         unsigned short* __restrict__ l,
                                         int n4, int idx, int stride)
{
    for (int i = idx; i < n4; i += stride) {
        float4 v = ((const float4*)in)[i];
        float f[4] = {v.x, v.y, v.z, v.w};
        unsigned short hb[4], lb[4];
        #pragma unroll
        for (int j = 0; j < 4; j++) {
            __nv_bfloat16 hi = __float2bfloat16(f[j]);
            hb[j] = __bfloat16_as_ushort(hi);
            float r = f[j] - __bfloat162float(hi);
            lb[j] = __bfloat16_as_ushort(__float2bfloat16(r));
        }
        *(uint2*)(h + (size_t)i * 4) = *(uint2*)hb;
        *(uint2*)(l + (size_t)i * 4) = *(uint2*)lb;
    }
}

__global__ void convert_inputs(const float* __restrict__ x,
                               const float* __restrict__ Wq,
                               const float* __restrict__ Wk,
                               const float* __restrict__ Wv,
                               const float* __restrict__ Ws1,
                               const float* __restrict__ Wo)
{
    const int idx = blockIdx.x * blockDim.x + threadIdx.x;
    const int stride = gridDim.x * blockDim.x;
    conv_seg(x,   g_xh,   g_xl,   MTOT*DD/4,  idx, stride);
    conv_seg(Wq,  g_wqh,  g_wql,  DD*DD/4,    idx, stride);
    conv_seg(Wk,  g_wkh,  g_wkl,  DD*DD/4,    idx, stride);
    conv_seg(Wv,  g_wvh,  g_wvl,  DD*DD/4,    idx, stride);
    conv_seg(Ws1, g_ws1h, g_ws1l, DD*(DD/2)/4, idx, stride);
    conv_seg(Wo,  g_woh,  g_wol,  DD*DD/4,    idx, stride);
}

__global__ void convert_att()
{
    const int idx = blockIdx.x * blockDim.x + threadIdx.x;
    const int stride = gridDim.x * blockDim.x;
    conv_seg(g_att, g_ath, g_atl, MTOT*DD/4, idx, stride);
}

// ---------------- bf16x3 tensor-core GEMM (fused multi-weight) -----------------
// C = A[M,K] @ W[K,N] + bias  with A,W split into bf16 hi+lo:
//   C = Ah*Wh + Ah*Wl + Al*Wh   (lo*lo term ~2^-32, dropped)
// 128x128 block tile, BK=16 per stage, 2-stage cp.async pipeline,
// ldmatrix fragment loads, m16n8k16 mma. Grid.x tiles select the weight segment.
struct Seg {
    const unsigned short* wh;
    const unsigned short* wl;
    const float* bias;
    float* c;
    int ldn;
    int relu;
};
struct Cfg { Seg s[4]; };

#define A_ROW 24     // 16 + 8 pad (halfs)
#define B_ROW 136    // 128 + 8 pad (halfs)
#define GITERS (DD/16)

__global__ __launch_bounds__(256, 2) void gemm_bf16x3(
    const unsigned short* __restrict__ Ah,
    const unsigned short* __restrict__ Al,
    Cfg cfg)
{
    __shared__ unsigned short smAh[2][128*A_ROW];
    __shared__ unsigned short smAl[2][128*A_ROW];
    __shared__ unsigned short smBh[2][16*B_ROW];
    __shared__ unsigned short smBl[2][16*B_ROW];

    const int tid  = threadIdx.x;
    const int lane = tid & 31;
    const int warp = tid >> 5;
    const int wm   = warp >> 2;       // 0..1
    const int wn   = warp & 3;        // 0..3

    const int bx = blockIdx.x;
    int seg = bx >> 3; if (seg > 3) seg = 3;
    const Seg sg = cfg.s[seg];
    const int col0 = (bx - seg * 8) * 128;
    const int bm   = blockIdx.y * 128;
    const int ldn  = sg.ldn;

    // ---- cp.async source pointers (advance per stage) ----
    const unsigned short* aSh = Ah + (size_t)(bm + (tid >> 1)) * DD + (tid & 1) * 8;
    const unsigned short* aSl = Al + (size_t)(bm + (tid >> 1)) * DD + (tid & 1) * 8;
    const unsigned short* bSh = sg.wh + (size_t)(tid >> 4) * ldn + col0 + (tid & 15) * 8;
    const unsigned short* bSl = sg.wl + (size_t)(tid >> 4) * ldn + col0 + (tid & 15) * 8;
    const size_t bStep = (size_t)16 * ldn;

    // ---- cp.async dest addresses ----
    uint32_t dAh[2], dAl[2], dBh[2], dBl[2];
    #pragma unroll
    for (int s = 0; s < 2; s++) {
        dAh[s] = (uint32_t)__cvta_generic_to_shared(&smAh[s][0]) + (tid >> 1) * (A_ROW*2) + (tid & 1) * 16;
        dAl[s] = (uint32_t)__cvta_generic_to_shared(&smAl[s][0]) + (tid >> 1) * (A_ROW*2) + (tid & 1) * 16;
        dBh[s] = (uint32_t)__cvta_generic_to_shared(&smBh[s][0]) + (tid >> 4) * (B_ROW*2) + (tid & 15) * 16;
        dBl[s] = (uint32_t)__cvta_generic_to_shared(&smBl[s][0]) + (tid >> 4) * (B_ROW*2) + (tid & 15) * 16;
    }

    // ---- ldmatrix lane addresses ----
    uint32_t aAdH[2], aAdL[2], bAdH[2], bAdL[2];
    #pragma unroll
    for (int s = 0; s < 2; s++) {
        const uint32_t aoff = (uint32_t)((wm*64 + (lane & 15)) * (A_ROW*2) + (lane >> 4) * 16);
        aAdH[s] = (uint32_t)__cvta_generic_to_shared(&smAh[s][0]) + aoff;
        aAdL[s] = (uint32_t)__cvta_generic_to_shared(&smAl[s][0]) + aoff;
        const uint32_t boff = (uint32_t)((lane & 15) * (B_ROW*2) + (lane >> 4) * 16 + wn * 64);
        bAdH[s] = (uint32_t)__cvta_generic_to_shared(&smBh[s][0]) + boff;
        bAdL[s] = (uint32_t)__cvta_generic_to_shared(&smBl[s][0]) + boff;
    }

    float acc[4][4][4];
    #pragma unroll
    for (int mt = 0; mt < 4; mt++)
        #pragma unroll
        for (int nt = 0; nt < 4; nt++)
            #pragma unroll
            for (int r = 0; r < 4; r++) acc[mt][nt][r] = 0.f;

    // prologue: stage 0
    CPA16(dAh[0], aSh); CPA16(dAl[0], aSl);
    CPA16(dBh[0], bSh); CPA16(dBl[0], bSl);
    asm volatile("cp.async.commit_group;");
    aSh += 16; aSl += 16; bSh += bStep; bSl += bStep;

    #pragma unroll 2
    for (int it = 0; it < GITERS; ++it) {
        if (it + 1 < GITERS) {
            const int sn = (it + 1) & 1;
            CPA16(dAh[sn], aSh); CPA16(dAl[sn], aSl);
            CPA16(dBh[sn], bSh); CPA16(dBl[sn], bSl);
            aSh += 16; aSl += 16; bSh += bStep; bSl += bStep;
        }
        asm volatile("cp.async.commit_group;");
        asm volatile("cp.async.wait_group 1;");
        __syncthreads();

        const int s = it & 1;
        uint32_t bh[8], bl[8];
        LDSM4T(&bh[0], bAdH[s]);
        LDSM4T(&bh[4], bAdH[s] + 32);
        LDSM4T(&bl[0], bAdL[s]);
        LDSM4T(&bl[4], bAdL[s] + 32);

        #pragma unroll
        for (int mt = 0; mt < 4; mt++) {
            uint32_t ah[4], al[4];
            LDSM4(ah, aAdH[s] + mt * (16*A_ROW*2));
            LDSM4(al, aAdL[s] + mt * (16*A_ROW*2));
            #pragma unroll
            for (int nt = 0; nt < 4; nt++) {
                MMA_BF16(acc[mt][nt], ah, &bh[nt*2]);
                MMA_BF16(acc[mt][nt], ah, &bl[nt*2]);
                MMA_BF16(acc[mt][nt], al, &bh[nt*2]);
            }
        }
        __syncthreads();
    }

    // epilogue
    const int g = lane >> 2;
    const int t = lane & 3;
    #pragma unroll
    for (int mt = 0; mt < 4; mt++) {
        const int r0 = bm + wm*64 + mt*16 + g;
        #pragma unroll
        for (int nt = 0; nt < 4; nt++) {
            const int cW = col0 + wn*32 + nt*8 + 2*t;   // column within this W
            const float b0 = sg.bias[cW], b1 = sg.bias[cW + 1];
            float v0 = acc[mt][nt][0] + b0;
            float v1 = acc[mt][nt][1] + b1;
            float v2 = acc[mt][nt][2] + b0;
            float v3 = acc[mt][nt][3] + b1;
            if (sg.relu) {
                v0 = fmaxf(v0, 0.f); v1 = fmaxf(v1, 0.f);
                v2 = fmaxf(v2, 0.f); v3 = fmaxf(v3, 0.f);
            }
            *(float2*)(sg.c + (size_t)r0 * ldn + cW)       = make_float2(v0, v1);
            *(float2*)(sg.c + (size_t)(r0 + 8) * ldn + cW) = make_float2(v2, v3);
        }
    }
}

// ---------------- indexer layer 2: imp[r] = hidden[r,:] . Ws2 ------------------
__global__ void indexer2_kernel(const float* __restrict__ hidden,
                                const float* __restrict__ Ws2)
{
    const int gw   = (blockIdx.x * blockDim.x + threadIdx.x) >> 5;
    const int lane = threadIdx.x & 31;
    if (gw >= MTOT) return;
    const float* hrow = hidden + (size_t)gw * (DD/2);
    float p = 0.f;
    #pragma unroll 4
    for (int c = lane; c < DD/2; c += 32) p = fmaf(hrow[c], Ws2[c], p);
    #pragma unroll
    for (int o = 16; o; o >>= 1) p += __shfl_xor_sync(0xffffffffu, p, o);
    if (lane == 0) g_imp[gw] = p;
}

// ---------------- top-K per batch (block per batch; iterative argmax) ----------
__global__ void topk_kernel()
{
    const int b   = blockIdx.x;
    const int tid = threadIdx.x;
    __shared__ float vals[SB];
    __shared__ float rv[256];
    __shared__ int   ri[256];

    for (int i = tid; i < SB; i += 256) {
        vals[i] = g_imp[b*SB + i];
        g_sel[b*SB + i] = 0;
    }
    __syncthreads();

    for (int tsel = 0; tsel < KSEL; tsel++) {
        float best = -INFINITY; int bi = SB;
        for (int i = tid; i < SB; i += 256) {
            float v = vals[i];
            if (v > best || (v == best && i < bi)) { best = v; bi = i; }
        }
        rv[tid] = best; ri[tid] = bi;
        __syncthreads();
        for (int s = 128; s > 0; s >>= 1) {
            if (tid < s) {
                if (rv[tid+s] > rv[tid] || (rv[tid+s] == rv[tid] && ri[tid+s] < ri[tid])) {
                    rv[tid] = rv[tid+s]; ri[tid] = ri[tid+s];
                }
            }
            __syncthreads();
        }
        if (tid == 0) {
            int w = ri[0];
            g_idx[b*KSEL + tsel] = w;
            g_sel[b*SB + w]      = 1;
            vals[w] = -INFINITY;
        }
        __syncthreads();
    }
}

// ---------------- gather selected K/V rows into compact [B, KSEL, D] -----------
__global__ void gather_kv_kernel()
{
    const int b = blockIdx.x >> 4;
    const int j = blockIdx.x & 15;
    const int src = g_idx[b*KSEL + j];
    const float4* kr = (const float4*)(g_k + (size_t)(b*SB + src) * DD);
    const float4* vr = (const float4*)(g_v + (size_t)(b*SB + src) * DD);
    float4* kd = (float4*)(g_ksel + (size_t)(b*KSEL + j) * DD);
    float4* vd = (float4*)(g_vsel + (size_t)(b*KSEL + j) * DD);
    kd[threadIdx.x] = kr[threadIdx.x];
    vd[threadIdx.x] = vr[threadIdx.x];
}

// ---------------- sparse attention: non-selected query rows --------------------
__global__ __launch_bounds__(256) void sparse_attn_kernel()
{
    const int lane = threadIdx.x & 31;
    const int gw   = (blockIdx.x * blockDim.x + threadIdx.x) >> 5;
    const int b = gw / (SB*HH);
    const int r = gw % (SB*HH);
    const int s = r / HH;
    const int h = r % HH;
    if (g_sel[b*SB + s]) return;   // warp-uniform

    const float* qrow = g_q + (size_t)(b*SB + s)*DD + h*DH;
    const float q0 = qrow[lane], q1 = qrow[lane + 32];

    float sc[KSEL];
    #pragma unroll
    for (int j = 0; j < KSEL; j++) {
        const float* kr = g_ksel + (size_t)(b*KSEL + j)*DD + h*DH;
        float p = q0*kr[lane] + q1*kr[lane + 32];
        #pragma unroll
        for (int o = 16; o; o >>= 1) p += __shfl_xor_sync(0xffffffffu, p, o);
        sc[j] = p * 0.125f;
    }
    float mx = -INFINITY;
    #pragma unroll
    for (int j = 0; j < KSEL; j++) mx = fmaxf(mx, sc[j]);
    float sum = 0.f;
    #pragma unroll
    for (int j = 0; j < KSEL; j++) { sc[j] = __expf(sc[j] - mx); sum += sc[j]; }
    const float inv = 1.f / sum;

    float o0 = 0.f, o1 = 0.f;
    #pragma unroll
    for (int j = 0; j < KSEL; j++) {
        const float* vr = g_vsel + (size_t)(b*KSEL + j)*DD + h*DH;
        o0 = fmaf(sc[j], vr[lane],      o0);
        o1 = fmaf(sc[j], vr[lane + 32], o1);
    }
    float* orow = g_att + (size_t)(b*SB + s)*DD + h*DH;
    orow[lane]      = o0 * inv;
    orow[lane + 32] = o1 * inv;
}

// ---------------- dense attention: the KSEL selected query rows ----------------
__global__ __launch_bounds__(256) void dense_attn_kernel()
{
    const int bi = blockIdx.x;
    const int b  = bi / (HH*KSEL);
    const int h  = (bi / KSEL) % HH;
    const int jq = bi % KSEL;
    const int s  = g_idx[b*KSEL + jq];

    __shared__ float qs[DH];
    __shared__ float sc[SB];
    __shared__ float red[256];
    __shared__ float part[4][DH];

    const int tid  = threadIdx.x;
    const int lane = tid & 31;
    const int w    = tid >> 5;

    if (tid < DH) qs[tid] = g_q[(size_t)(b*SB + s)*DD + h*DH + tid];
    __syncthreads();
    const float q0 = qs[lane], q1 = qs[lane + 32];

    for (int j = w; j < SB; j += 8) {
        const float* kr = g_k + (size_t)(b*SB + j)*DD + h*DH;
        float p = q0*kr[lane] + q1*kr[lane + 32];
        #pragma unroll
        for (int o = 16; o; o >>= 1) p += __shfl_xor_sync(0xffffffffu, p, o);
        if (lane == 0) sc[j] = p * 0.125f;
    }
    __syncthreads();

    float mx = -INFINITY;
    for (int j = tid; j < SB; j += 256) mx = fmaxf(mx, sc[j]);
    red[tid] = mx; __syncthreads();
    for (int st = 128; st; st >>= 1) {
        if (tid < st) red[tid] = fmaxf(red[tid], red[tid + st]);
        __syncthreads();
    }
    mx = red[0];
    __syncthreads();

    float lsum = 0.f;
    for (int j = tid; j < SB; j += 256) {
        float e = __expf(sc[j] - mx);
        sc[j] = e;
        lsum += e;
    }
    red[tid] = lsum; __syncthreads();
    for (int st = 128; st; st >>= 1) {
        if (tid < st) red[tid] += red[tid + st];
        __syncthreads();
    }
    const float inv = 1.f / red[0];

    const int d = tid & 63;
    const int c = tid >> 6;
    float acc = 0.f;
    const int j0 = c * (SB/4), j1 = j0 + (SB/4);
    for (int j = j0; j < j1; j++)
        acc = fmaf(sc[j], g_v[(size_t)(b*SB + j)*DD + h*DH + d], acc);
    part[c][d] = acc;
    __syncthreads();
    if (tid < DH) {
        float r = (part[0][tid] + part[1][tid] + part[2][tid] + part[3][tid]) * inv;
        g_att[(size_t)(b*SB + s)*DD + h*DH + tid] = r;
    }
}

// ---------------- launch -------------------------------------------------------
extern "C" void kernel_launch(void* const* d_in, const int* in_sizes, int n_in,
                              void* d_out, int out_size)
{
    const float* x   = (const float*)d_in[0];
    const float* bq  = (const float*)d_in[2];
    const float* bk  = (const float*)d_in[4];
    const float* bv  = (const float*)d_in[6];
    const float* bo  = (const float*)d_in[8];
    const float* bs1 = (const float*)d_in[10];
    const float* Ws2 = (const float*)d_in[11];
    float* out = (float*)d_out;

    float *q, *k, *v, *att, *hidden;
    cudaGetSymbolAddress((void**)&q,      g_q);
    cudaGetSymbolAddress((void**)&k,      g_k);
    cudaGetSymbolAddress((void**)&v,      g_v);
    cudaGetSymbolAddress((void**)&att,    g_att);
    cudaGetSymbolAddress((void**)&hidden, g_hidden);

    unsigned short *xh, *xl, *wqh, *wql, *wkh, *wkl, *wvh, *wvl;
    unsigned short *ws1h, *ws1l, *woh, *wol, *ath, *atl;
    cudaGetSymbolAddress((void**)&xh,   g_xh);
    cudaGetSymbolAddress((void**)&xl,   g_xl);
    cudaGetSymbolAddress((void**)&wqh,  g_wqh);
    cudaGetSymbolAddress((void**)&wql,  g_wql);
    cudaGetSymbolAddress((void**)&wkh,  g_wkh);
    cudaGetSymbolAddress((void**)&wkl,  g_wkl);
    cudaGetSymbolAddress((void**)&wvh,  g_wvh);
    cudaGetSymbolAddress((void**)&wvl,  g_wvl);
    cudaGetSymbolAddress((void**)&ws1h, g_ws1h);
    cudaGetSymbolAddress((void**)&ws1l, g_ws1l);
    cudaGetSymbolAddress((void**)&woh,  g_woh);
    cudaGetSymbolAddress((void**)&wol,  g_wol);
    cudaGetSymbolAddress((void**)&ath,  g_ath);
    cudaGetSymbolAddress((void**)&atl,  g_atl);

    dim3 t256(256);

    // 1. convert x + all weights to bf16 hi/lo
    convert_inputs<<<1024, t256>>>(x, (const float*)d_in[1], (const float*)d_in[3],
                                   (const float*)d_in[5], (const float*)d_in[9],
                                   (const float*)d_in[7]);

    // 2. fused QKV + indexer-L1 GEMM (bf16x3 tensor cores)
    Cfg cfg1;
    cfg1.s[0] = {wqh,  wql,  bq,  q,      DD,   0};
    cfg1.s[1] = {wkh,  wkl,  bk,  k,      DD,   0};
    cfg1.s[2] = {wvh,  wvl,  bv,  v,      DD,   0};
    cfg1.s[3] = {ws1h, ws1l, bs1, hidden, DD/2, 1};
    gemm_bf16x3<<<dim3(28, 32), t256>>>(xh, xl, cfg1);

    // 3. indexer layer 2 -> importance logits (sigmoid skipped; monotonic)
    indexer2_kernel<<<(MTOT*32 + 255)/256, t256>>>(hidden, Ws2);

    // 4. top-k + gather
    topk_kernel<<<NB, t256>>>();
    gather_kv_kernel<<<NB*KSEL, t256>>>();

    // 5. attention (sparse rows + dense selected rows cover all rows exactly once)
    sparse_attn_kernel<<<(NB*SB*HH)/8, t256>>>();
    dense_attn_kernel<<<NB*HH*KSEL, t256>>>();

    // 6. convert att, then output projection -> d_out
    convert_att<<<1024, t256>>>();
    Cfg cfg2;
    cfg2.s[0] = {woh, wol, bo, out, DD, 0};
    cfg2.s[1] = cfg2.s[0];
    cfg2.s[2] = cfg2.s[0];
    cfg2.s[3] = cfg2.s[0];
    gemm_bf16x3<<<dim3(8, 32), t256>>>(ath, atl, cfg2);
}